// round 2
// baseline (speedup 1.0000x reference)
#include <cuda_runtime.h>
#include <math.h>

#define HH 2048
#define WW 2048
#define NIMG 4
#define TOT (NIMG*HH*WW)
#define RANK0 8388607u   // (TOT-1)/2

// harris tile geometry
#define TR 64            // output tile rows
#define TC 32            // output tile cols
#define GR 72            // TR+8 (gauss halo)
#define SXR 74           // TR+10
#define SXC 42           // TC+10
#define PIX 41           // pitch for Ix/Iy (conflict-free)
#define PSH 33           // pitch for smoothed channels
#define SIXY (GR*PIX)            // 2952 floats
#define SHCH (GR*PSH)            // 2376 floats per channel
#define SC_FLOATS (3*SHCH)       // 7128 (>= SXR*SXC=3108)
#define SMEM_FLOATS (2*SIXY + SC_FLOATS)   // 13032
#define SMEM_BYTES (SMEM_FLOATS*4)         // 52128
#define HARRIS_BLOCKS ((WW/TC)*(HH/TR)*NIMG)  // 64*32*4 = 8192

// ---------------- device scratch ----------------
__device__ float    g_R[TOT];
__device__ unsigned g_cand[TOT];
__device__ unsigned g_hist[2048];
__device__ unsigned g_prefix, g_rank, g_cand_n;
__device__ unsigned g_done1, g_done2, g_done3;
__device__ float    g_med;

// ---------------- shared select (run by one block, 256 threads) ----------------
__device__ __forceinline__ void select_pass(int shift, int nbits) {
    __shared__ unsigned ssum[256];
    const int nb = 1 << nbits;
    const int per = nb >> 8;               // 8 or 4
    const int t = threadIdx.x;
    unsigned pfx, rank;
    if (shift == 21) { pfx = 0u; rank = RANK0; }
    else             { pfx = g_prefix; rank = g_rank; }

    unsigned local[8];
    unsigned sum = 0;
    for (int i = 0; i < per; i++) { local[i] = g_hist[t*per + i]; sum += local[i]; }
    ssum[t] = sum;
    __syncthreads();
    unsigned run = sum;
    for (int d = 1; d < 256; d <<= 1) {
        unsigned add = (t >= d) ? ssum[t - d] : 0u;
        __syncthreads();
        run += add;
        ssum[t] = run;
        __syncthreads();
    }
    unsigned before = run - sum;
    if (rank >= before && rank < run) {
        unsigned cum = before;
        for (int i = 0; i < per; i++) {
            if (rank < cum + local[i]) {
                unsigned bin = (unsigned)(t*per + i);
                unsigned np = pfx | (bin << shift);
                g_prefix = np;
                g_rank = rank - cum;
                if (shift == 0) {
                    unsigned bb = (np & 0x80000000u) ? (np ^ 0x80000000u) : ~np;
                    g_med = __uint_as_float(bb);
                }
                break;
            }
            cum += local[i];
        }
    }
    __syncthreads();
    for (int i = t; i < nb; i += 256) g_hist[i] = 0;   // leave clean for next pass/run
}

// ---------------- fused Sobel + products + separable 9x9 gauss + R + hist1 ----------------
__global__ __launch_bounds__(256) void k_harris(const float* __restrict__ x,
                                                const float* __restrict__ g2) {
    extern __shared__ float smem[];
    float* sIx = smem;                 // GR x PIX
    float* sIy = smem + SIXY;          // GR x PIX
    float* sC  = smem + 2*SIXY;        // union: sx (SXR*SXC) then sh[3] (GR*PSH each)
    unsigned* shist = (unsigned*)smem; // aliases sIx after horiz phase (2048 <= SIXY)

    __shared__ float s_w[9];
    __shared__ unsigned s_last;

    const int t = threadIdx.x;
    const int n   = blockIdx.z;
    const int r0g = blockIdx.y * TR;
    const int c0g = blockIdx.x * TC;
    const float* __restrict__ xi = x + (size_t)n * HH * WW;

    if (t == 0) {
        double c = sqrt((double)g2[4*9 + 4]);
        for (int k = 0; k < 9; k++) s_w[k] = (float)((double)g2[4*9 + k] / c);
    }

    // ---- load x tile (zero padded), rows -5..68, cols -5..36 ----
    for (int idx = t; idx < SXR*SXC; idx += 256) {
        int i = idx / SXC, j = idx % SXC;
        int gr = r0g + i - 5, gc = c0g + j - 5;
        float v = 0.f;
        if (gr >= 0 && gr < HH && gc >= 0 && gc < WW) v = xi[(size_t)gr * WW + gc];
        sC[idx] = v;
    }
    __syncthreads();

    float w[9];
    #pragma unroll
    for (int k = 0; k < 9; k++) w[k] = s_w[k];

    // ---- sobel: Ix,Iy at rel rows -4..67 (i=0..71), rel cols -4..35 (j=0..39) ----
    for (int task = t; task < GR*10; task += 256) {
        int i  = task / 10;
        int j0 = (task % 10) * 4;
        float a[3][6];
        #pragma unroll
        for (int r = 0; r < 3; r++)
            #pragma unroll
            for (int c = 0; c < 6; c++)
                a[r][c] = sC[(i + r)*SXC + j0 + c];
        int gr = r0g + i - 4;
        bool rok = (gr >= 0 && gr < HH);
        #pragma unroll
        for (int dj = 0; dj < 4; dj++) {
            int gc = c0g + j0 + dj - 4;
            float ix = 0.f, iy = 0.f;
            if (rok && gc >= 0 && gc < WW) {
                ix = (a[0][dj+2]-a[0][dj]) + 2.f*(a[1][dj+2]-a[1][dj]) + (a[2][dj+2]-a[2][dj]);
                iy = (a[2][dj]-a[0][dj])   + 2.f*(a[2][dj+1]-a[0][dj+1]) + (a[2][dj+2]-a[0][dj+2]);
            }
            sIx[i*PIX + j0 + dj] = ix;
            sIy[i*PIX + j0 + dj] = iy;
        }
    }
    __syncthreads();   // sx (sC) now dead

    // ---- horizontal gauss of the 3 products (products formed on the fly) ----
    // outputs: sh[ch][row 0..71][col 0..31]
    for (int task = t; task < GR*8; task += 256) {
        int row = task >> 3;
        int j0  = (task & 7) << 2;
        float s0[4] = {0,0,0,0}, s1[4] = {0,0,0,0}, s2[4] = {0,0,0,0};
        #pragma unroll
        for (int p = 0; p < 12; p++) {
            float ix = sIx[row*PIX + j0 + p];
            float iy = sIy[row*PIX + j0 + p];
            float pxx = ix*ix, pyy = iy*iy, pxy = ix*iy;
            #pragma unroll
            for (int j = 0; j < 4; j++) {
                int k = p - j;
                if (k >= 0 && k <= 8) {
                    s0[j] += w[k]*pxx;
                    s1[j] += w[k]*pyy;
                    s2[j] += w[k]*pxy;
                }
            }
        }
        #pragma unroll
        for (int j = 0; j < 4; j++) {
            sC[0*SHCH + row*PSH + j0 + j] = s0[j];
            sC[1*SHCH + row*PSH + j0 + j] = s1[j];
            sC[2*SHCH + row*PSH + j0 + j] = s2[j];
        }
    }
    __syncthreads();   // sIx/sIy now dead

    // zero block histogram (aliases sIx region)
    for (int i = t; i < 2048; i += 256) shist[i] = 0;
    __syncthreads();

    // ---- vertical gauss + R + histogram ----
    {
        const int col = t & 31;
        const int r0l = (t >> 5) * 8;
        const unsigned lane = t & 31;
        float win[16], s0[8], s1[8];

        #pragma unroll
        for (int k = 0; k < 16; k++) win[k] = sC[0*SHCH + (r0l + k)*PSH + col];
        #pragma unroll
        for (int o = 0; o < 8; o++) {
            float s = 0.f;
            #pragma unroll
            for (int k = 0; k < 9; k++) s += w[k]*win[o + k];
            s0[o] = s;
        }
        #pragma unroll
        for (int k = 0; k < 16; k++) win[k] = sC[1*SHCH + (r0l + k)*PSH + col];
        #pragma unroll
        for (int o = 0; o < 8; o++) {
            float s = 0.f;
            #pragma unroll
            for (int k = 0; k < 9; k++) s += w[k]*win[o + k];
            s1[o] = s;
        }
        #pragma unroll
        for (int k = 0; k < 16; k++) win[k] = sC[2*SHCH + (r0l + k)*PSH + col];

        size_t obase = (size_t)n * HH * WW + (size_t)(r0g + r0l) * WW + (c0g + col);
        #pragma unroll
        for (int o = 0; o < 8; o++) {
            float s2 = 0.f;
            #pragma unroll
            for (int k = 0; k < 9; k++) s2 += w[k]*win[o + k];
            float det = s0[o]*s1[o] - s2*s2;
            float tr  = s0[o] + s1[o];
            float R   = det - 0.05f*tr*tr;
            g_R[obase + (size_t)o * WW] = R;

            unsigned b = __float_as_uint(R);
            unsigned u = b ^ ((b & 0x80000000u) ? 0xFFFFFFFFu : 0x80000000u);
            unsigned bin = u >> 21;
            unsigned peers = __match_any_sync(0xFFFFFFFFu, bin);
            if ((unsigned)(__ffs(peers) - 1) == lane)
                atomicAdd(&shist[bin], (unsigned)__popc(peers));
        }
    }
    __syncthreads();

    // flush to global hist
    for (int i = t; i < 2048; i += 256) {
        unsigned c = shist[i];
        if (c) atomicAdd(&g_hist[i], c);
    }
    __threadfence();
    if (t == 0) s_last = (atomicAdd(&g_done1, 1) == HARRIS_BLOCKS - 1) ? 1u : 0u;
    __syncthreads();
    if (s_last) {
        __threadfence();
        select_pass(21, 11);
        if (t == 0) { g_done1 = 0; g_cand_n = 0; }
    }
}

// ---------------- pass 2: hist bits 20..10 of matching values + compaction + select ----------------
__global__ __launch_bounds__(256) void k_hist2() {
    __shared__ unsigned s_hist[2048];
    __shared__ unsigned s_last;
    for (int i = threadIdx.x; i < 2048; i += 256) s_hist[i] = 0;
    __syncthreads();

    const unsigned pfx_hi = g_prefix >> 21;
    const unsigned lane = threadIdx.x & 31;
    const float4* __restrict__ Rv = (const float4*)g_R;
    const size_t n4 = TOT / 4;
    const size_t stride = (size_t)gridDim.x * 256;

    for (size_t i4 = (size_t)blockIdx.x * 256 + threadIdx.x; i4 < n4; i4 += stride) {
        float4 v = Rv[i4];
        float vals[4] = {v.x, v.y, v.z, v.w};
        #pragma unroll
        for (int e = 0; e < 4; e++) {
            unsigned b = __float_as_uint(vals[e]);
            unsigned u = b ^ ((b & 0x80000000u) ? 0xFFFFFFFFu : 0x80000000u);
            bool match = ((u >> 21) == pfx_hi);
            unsigned bal = __ballot_sync(0xFFFFFFFFu, match);
            if (bal) {
                unsigned base = 0;
                int leader = __ffs(bal) - 1;
                if ((int)lane == leader) base = atomicAdd(&g_cand_n, (unsigned)__popc(bal));
                base = __shfl_sync(0xFFFFFFFFu, base, leader);
                if (match) {
                    unsigned off = __popc(bal & ((1u << lane) - 1u));
                    g_cand[base + off] = u;
                    unsigned bin = (u >> 10) & 2047u;
                    unsigned peers = __match_any_sync(bal, bin);
                    if ((unsigned)(__ffs(peers) - 1) == lane)
                        atomicAdd(&s_hist[bin], (unsigned)__popc(peers));
                }
            }
        }
    }
    __syncthreads();
    for (int i = threadIdx.x; i < 2048; i += 256) {
        unsigned c = s_hist[i];
        if (c) atomicAdd(&g_hist[i], c);
    }
    __threadfence();
    if (threadIdx.x == 0) s_last = (atomicAdd(&g_done2, 1) == gridDim.x - 1) ? 1u : 0u;
    __syncthreads();
    if (s_last) {
        __threadfence();
        select_pass(10, 11);
        if (threadIdx.x == 0) g_done2 = 0;
    }
}

// ---------------- pass 3: low 10 bits over compacted candidates + final select ----------------
__global__ __launch_bounds__(256) void k_hist3() {
    __shared__ unsigned s_hist[1024];
    __shared__ unsigned s_last;
    for (int i = threadIdx.x; i < 1024; i += 256) s_hist[i] = 0;
    __syncthreads();

    const unsigned pfx = g_prefix >> 10;
    const unsigned total = g_cand_n;
    const unsigned lane = threadIdx.x & 31;

    for (unsigned base = blockIdx.x * 256; base < total; base += gridDim.x * 256) {
        unsigned i = base + threadIdx.x;
        bool m = false; unsigned bin = 0;
        if (i < total) {
            unsigned u = g_cand[i];
            m = ((u >> 10) == pfx);
            bin = u & 1023u;
        }
        unsigned bal = __ballot_sync(0xFFFFFFFFu, m);
        if (m) {
            unsigned peers = __match_any_sync(bal, bin);
            if ((unsigned)(__ffs(peers) - 1) == lane)
                atomicAdd(&s_hist[bin], (unsigned)__popc(peers));
        }
    }
    __syncthreads();
    for (int i = threadIdx.x; i < 1024; i += 256) {
        unsigned c = s_hist[i];
        if (c) atomicAdd(&g_hist[i], c);
    }
    __threadfence();
    if (threadIdx.x == 0) s_last = (atomicAdd(&g_done3, 1) == gridDim.x - 1) ? 1u : 0u;
    __syncthreads();
    if (s_last) {
        __threadfence();
        select_pass(0, 10);
        if (threadIdx.x == 0) g_done3 = 0;
    }
}

// ---------------- threshold + 7x7 NMS ----------------
__global__ __launch_bounds__(256) void k_pool(float* __restrict__ out) {
    __shared__ float sxt[38][40];
    __shared__ float srm[38][33];
    const int bx = blockIdx.x, by = blockIdx.y, n = blockIdx.z;
    const int r0 = by * 32, c0 = bx * 32;
    const float* __restrict__ Ri = g_R + (size_t)n * HH * WW;
    const float med = g_med;
    const float NEG_INF = __int_as_float(0xFF800000);

    for (int idx = threadIdx.x; idx < 38*38; idx += 256) {
        int i = idx / 38, j = idx % 38;
        int gr = r0 + i - 3, gc = c0 + j - 3;
        float v = NEG_INF;
        if (gr >= 0 && gr < HH && gc >= 0 && gc < WW) {
            float R = Ri[(size_t)gr * WW + gc];
            v = (R > med) ? R : 0.f;
        }
        sxt[i][j] = v;
    }
    __syncthreads();

    for (int idx = threadIdx.x; idx < 38*32; idx += 256) {
        int i = idx / 32, j = idx % 32;
        float m = sxt[i][j];
        #pragma unroll
        for (int k = 1; k < 7; k++) m = fmaxf(m, sxt[i][j+k]);
        srm[i][j] = m;
    }
    __syncthreads();

    for (int idx = threadIdx.x; idx < 32*32; idx += 256) {
        int r = idx / 32, c = idx % 32;
        float m = srm[r][c];
        #pragma unroll
        for (int k = 1; k < 7; k++) m = fmaxf(m, srm[r+k][c]);
        float xt = sxt[r+3][c+3];
        out[(size_t)n * HH * WW + (size_t)(r0 + r) * WW + (c0 + c)] = (xt == m) ? xt : 0.f;
    }
}

// ---------------- launch ----------------
extern "C" void kernel_launch(void* const* d_in, const int* in_sizes, int n_in,
                              void* d_out, int out_size) {
    const float* x     = (const float*)d_in[0];
    const float* gauss = (const float*)d_in[2];
    float* out = (float*)d_out;

    cudaFuncSetAttribute(k_harris, cudaFuncAttributeMaxDynamicSharedMemorySize, SMEM_BYTES);

    dim3 gh(WW/TC, HH/TR, NIMG);     // 64 x 32 x 4
    k_harris<<<gh, 256, SMEM_BYTES>>>(x, gauss);

    k_hist2<<<1024, 256>>>();
    k_hist3<<<128, 256>>>();

    dim3 gp(WW/32, HH/32, NIMG);
    k_pool<<<gp, 256>>>(out);
}

// round 3
// speedup vs baseline: 2.0179x; 2.0179x over previous
#include <cuda_runtime.h>
#include <math.h>

#define HH 2048
#define WW 2048
#define NIMG 4
#define TOT (NIMG*HH*WW)
#define RANK0 8388607u   // (TOT-1)/2

// harris tile geometry
#define TR 64
#define TC 32
#define GR 72            // TR+8
#define SXR 74           // TR+10
#define SXC 42           // TC+10
#define PIX 41
#define PSH 33
#define SIXY (GR*PIX)
#define SHCH (GR*PSH)
#define SC_FLOATS (3*SHCH)
#define SMEM_FLOATS (2*SIXY + SC_FLOATS)
#define SMEM_BYTES (SMEM_FLOATS*4)
#define HARRIS_BLOCKS ((WW/TC)*(HH/TR)*NIMG)

// ---------------- device scratch ----------------
__device__ float    g_R[TOT];
__device__ unsigned g_hist[2048];
__device__ unsigned g_prefix, g_rank;
__device__ unsigned g_done1, g_done2, g_done3;
__device__ float    g_med;

// ---------------- shared select (one block, 256 threads) ----------------
__device__ __forceinline__ void select_pass(int shift, int nbits) {
    __shared__ unsigned ssum[256];
    const int nb = 1 << nbits;
    const int per = nb >> 8;
    const int t = threadIdx.x;
    unsigned pfx, rank;
    if (shift == 21) { pfx = 0u; rank = RANK0; }
    else             { pfx = g_prefix; rank = g_rank; }

    unsigned local[8];
    unsigned sum = 0;
    for (int i = 0; i < per; i++) { local[i] = g_hist[t*per + i]; sum += local[i]; }
    ssum[t] = sum;
    __syncthreads();
    unsigned run = sum;
    for (int d = 1; d < 256; d <<= 1) {
        unsigned add = (t >= d) ? ssum[t - d] : 0u;
        __syncthreads();
        run += add;
        ssum[t] = run;
        __syncthreads();
    }
    unsigned before = run - sum;
    if (rank >= before && rank < run) {
        unsigned cum = before;
        for (int i = 0; i < per; i++) {
            if (rank < cum + local[i]) {
                unsigned bin = (unsigned)(t*per + i);
                unsigned np = pfx | (bin << shift);
                g_prefix = np;
                g_rank = rank - cum;
                if (shift == 0) {
                    unsigned bb = (np & 0x80000000u) ? (np ^ 0x80000000u) : ~np;
                    g_med = __uint_as_float(bb);
                }
                break;
            }
            cum += local[i];
        }
    }
    __syncthreads();
    for (int i = t; i < nb; i += 256) g_hist[i] = 0;
}

// ---------------- fused Sobel + products + separable gauss + R + hist1 ----------------
__global__ __launch_bounds__(256) void k_harris(const float* __restrict__ x,
                                                const float* __restrict__ g2) {
    extern __shared__ float smem[];
    float* sIx = smem;
    float* sIy = smem + SIXY;
    float* sC  = smem + 2*SIXY;
    unsigned* shist = (unsigned*)smem;   // aliases sIx after horiz phase

    __shared__ float s_w[9];
    __shared__ unsigned s_last;

    const int t = threadIdx.x;
    const int n   = blockIdx.z;
    const int r0g = blockIdx.y * TR;
    const int c0g = blockIdx.x * TC;
    const float* __restrict__ xi = x + (size_t)n * HH * WW;

    if (t == 0) {
        double c = sqrt((double)g2[4*9 + 4]);
        for (int k = 0; k < 9; k++) s_w[k] = (float)((double)g2[4*9 + k] / c);
    }

    const bool interior = (blockIdx.x > 0) && (blockIdx.x < WW/TC - 1) &&
                          (blockIdx.y > 0) && (blockIdx.y < HH/TR - 1);

    // ---- load x tile ----
    if (interior) {
        const float* base = xi + (size_t)(r0g - 5) * WW + (c0g - 5);
        for (int idx = t; idx < SXR*SXC; idx += 256) {
            int i = idx / SXC, j = idx % SXC;
            sC[idx] = base[(size_t)i * WW + j];
        }
    } else {
        for (int idx = t; idx < SXR*SXC; idx += 256) {
            int i = idx / SXC, j = idx % SXC;
            int gr = r0g + i - 5, gc = c0g + j - 5;
            float v = 0.f;
            if (gr >= 0 && gr < HH && gc >= 0 && gc < WW) v = xi[(size_t)gr * WW + gc];
            sC[idx] = v;
        }
    }
    __syncthreads();

    float w[9];
    #pragma unroll
    for (int k = 0; k < 9; k++) w[k] = s_w[k];

    // ---- sobel: Ix,Iy at rel rows -4..67, rel cols -4..35 ----
    for (int task = t; task < GR*10; task += 256) {
        int i  = task / 10;
        int j0 = (task % 10) * 4;
        float a[3][6];
        #pragma unroll
        for (int r = 0; r < 3; r++)
            #pragma unroll
            for (int c = 0; c < 6; c++)
                a[r][c] = sC[(i + r)*SXC + j0 + c];
        if (interior) {
            #pragma unroll
            for (int dj = 0; dj < 4; dj++) {
                float ix = (a[0][dj+2]-a[0][dj]) + 2.f*(a[1][dj+2]-a[1][dj]) + (a[2][dj+2]-a[2][dj]);
                float iy = (a[2][dj]-a[0][dj])   + 2.f*(a[2][dj+1]-a[0][dj+1]) + (a[2][dj+2]-a[0][dj+2]);
                sIx[i*PIX + j0 + dj] = ix;
                sIy[i*PIX + j0 + dj] = iy;
            }
        } else {
            int gr = r0g + i - 4;
            bool rok = (gr >= 0 && gr < HH);
            #pragma unroll
            for (int dj = 0; dj < 4; dj++) {
                int gc = c0g + j0 + dj - 4;
                float ix = 0.f, iy = 0.f;
                if (rok && gc >= 0 && gc < WW) {
                    ix = (a[0][dj+2]-a[0][dj]) + 2.f*(a[1][dj+2]-a[1][dj]) + (a[2][dj+2]-a[2][dj]);
                    iy = (a[2][dj]-a[0][dj])   + 2.f*(a[2][dj+1]-a[0][dj+1]) + (a[2][dj+2]-a[0][dj+2]);
                }
                sIx[i*PIX + j0 + dj] = ix;
                sIy[i*PIX + j0 + dj] = iy;
            }
        }
    }
    __syncthreads();

    // ---- horizontal gauss of products (products on the fly, constant indices) ----
    for (int task = t; task < GR*8; task += 256) {
        int row = task >> 3;
        int j0  = (task & 7) << 2;
        const float* bx = &sIx[row*PIX + j0];
        const float* by = &sIy[row*PIX + j0];
        float ix[12], iy[12];
        #pragma unroll
        for (int p = 0; p < 12; p++) { ix[p] = bx[p]; iy[p] = by[p]; }
        float s0[4] = {0,0,0,0}, s1[4] = {0,0,0,0}, s2[4] = {0,0,0,0};
        #pragma unroll
        for (int p = 0; p < 12; p++) {
            float pxx = ix[p]*ix[p];
            float pyy = iy[p]*iy[p];
            float pxy = ix[p]*iy[p];
            #pragma unroll
            for (int j = 0; j < 4; j++) {
                if (p - j >= 0 && p - j <= 8) {
                    float wk = w[p - j];
                    s0[j] += wk*pxx;
                    s1[j] += wk*pyy;
                    s2[j] += wk*pxy;
                }
            }
        }
        #pragma unroll
        for (int j = 0; j < 4; j++) {
            sC[0*SHCH + row*PSH + j0 + j] = s0[j];
            sC[1*SHCH + row*PSH + j0 + j] = s1[j];
            sC[2*SHCH + row*PSH + j0 + j] = s2[j];
        }
    }
    __syncthreads();

    for (int i = t; i < 2048; i += 256) shist[i] = 0;
    __syncthreads();

    // ---- vertical gauss + R + histogram ----
    {
        const int col = t & 31;
        const int r0l = (t >> 5) * 8;
        const unsigned lane = t & 31;
        float win[16], s0[8], s1[8];

        #pragma unroll
        for (int k = 0; k < 16; k++) win[k] = sC[0*SHCH + (r0l + k)*PSH + col];
        #pragma unroll
        for (int o = 0; o < 8; o++) {
            float s = 0.f;
            #pragma unroll
            for (int k = 0; k < 9; k++) s += w[k]*win[o + k];
            s0[o] = s;
        }
        #pragma unroll
        for (int k = 0; k < 16; k++) win[k] = sC[1*SHCH + (r0l + k)*PSH + col];
        #pragma unroll
        for (int o = 0; o < 8; o++) {
            float s = 0.f;
            #pragma unroll
            for (int k = 0; k < 9; k++) s += w[k]*win[o + k];
            s1[o] = s;
        }
        #pragma unroll
        for (int k = 0; k < 16; k++) win[k] = sC[2*SHCH + (r0l + k)*PSH + col];

        size_t obase = (size_t)n * HH * WW + (size_t)(r0g + r0l) * WW + (c0g + col);
        #pragma unroll
        for (int o = 0; o < 8; o++) {
            float s2 = 0.f;
            #pragma unroll
            for (int k = 0; k < 9; k++) s2 += w[k]*win[o + k];
            float det = s0[o]*s1[o] - s2*s2;
            float tr  = s0[o] + s1[o];
            float R   = det - 0.05f*tr*tr;
            g_R[obase + (size_t)o * WW] = R;

            unsigned b = __float_as_uint(R);
            unsigned u = b ^ ((b & 0x80000000u) ? 0xFFFFFFFFu : 0x80000000u);
            unsigned bin = u >> 21;
            unsigned peers = __match_any_sync(0xFFFFFFFFu, bin);
            if ((unsigned)(__ffs(peers) - 1) == lane)
                atomicAdd(&shist[bin], (unsigned)__popc(peers));
        }
    }
    __syncthreads();

    for (int i = t; i < 2048; i += 256) {
        unsigned c = shist[i];
        if (c) atomicAdd(&g_hist[i], c);
    }
    __threadfence();
    if (t == 0) s_last = (atomicAdd(&g_done1, 1) == HARRIS_BLOCKS - 1) ? 1u : 0u;
    __syncthreads();
    if (s_last) {
        __threadfence();
        select_pass(21, 11);
        if (t == 0) g_done1 = 0;
    }
}

// ---------------- pass 2: full scan, match top-11, hist bits 20..10, fused select ----------------
__global__ __launch_bounds__(256) void k_hist2() {
    __shared__ unsigned s_hist[2048];
    __shared__ unsigned s_last;
    for (int i = threadIdx.x; i < 2048; i += 256) s_hist[i] = 0;
    __syncthreads();

    const unsigned pfx_hi = g_prefix >> 21;
    const unsigned lane = threadIdx.x & 31;
    const float4* __restrict__ Rv = (const float4*)g_R;
    const size_t n4 = TOT / 4;
    const size_t stride = (size_t)gridDim.x * 256;

    for (size_t i4 = (size_t)blockIdx.x * 256 + threadIdx.x; i4 < n4; i4 += stride) {
        float4 v = Rv[i4];
        float vals[4] = {v.x, v.y, v.z, v.w};
        #pragma unroll
        for (int e = 0; e < 4; e++) {
            unsigned b = __float_as_uint(vals[e]);
            unsigned u = b ^ ((b & 0x80000000u) ? 0xFFFFFFFFu : 0x80000000u);
            bool match = ((u >> 21) == pfx_hi);
            unsigned bin = (u >> 10) & 2047u;
            unsigned bal = __ballot_sync(0xFFFFFFFFu, match);
            if (match) {
                unsigned peers = __match_any_sync(bal, bin);
                if ((unsigned)(__ffs(peers) - 1) == lane)
                    atomicAdd(&s_hist[bin], (unsigned)__popc(peers));
            }
        }
    }
    __syncthreads();
    for (int i = threadIdx.x; i < 2048; i += 256) {
        unsigned c = s_hist[i];
        if (c) atomicAdd(&g_hist[i], c);
    }
    __threadfence();
    if (threadIdx.x == 0) s_last = (atomicAdd(&g_done2, 1) == gridDim.x - 1) ? 1u : 0u;
    __syncthreads();
    if (s_last) {
        __threadfence();
        select_pass(10, 11);
        if (threadIdx.x == 0) g_done2 = 0;
    }
}

// ---------------- pass 3: full scan, match top-22, hist bits 9..0, fused select ----------------
__global__ __launch_bounds__(256) void k_hist3() {
    __shared__ unsigned s_hist[1024];
    __shared__ unsigned s_last;
    for (int i = threadIdx.x; i < 1024; i += 256) s_hist[i] = 0;
    __syncthreads();

    const unsigned pfx = g_prefix >> 10;
    const unsigned lane = threadIdx.x & 31;
    const float4* __restrict__ Rv = (const float4*)g_R;
    const size_t n4 = TOT / 4;
    const size_t stride = (size_t)gridDim.x * 256;

    for (size_t i4 = (size_t)blockIdx.x * 256 + threadIdx.x; i4 < n4; i4 += stride) {
        float4 v = Rv[i4];
        float vals[4] = {v.x, v.y, v.z, v.w};
        #pragma unroll
        for (int e = 0; e < 4; e++) {
            unsigned b = __float_as_uint(vals[e]);
            unsigned u = b ^ ((b & 0x80000000u) ? 0xFFFFFFFFu : 0x80000000u);
            bool match = ((u >> 10) == pfx);
            unsigned bin = u & 1023u;
            unsigned bal = __ballot_sync(0xFFFFFFFFu, match);
            if (match) {
                unsigned peers = __match_any_sync(bal, bin);
                if ((unsigned)(__ffs(peers) - 1) == lane)
                    atomicAdd(&s_hist[bin], (unsigned)__popc(peers));
            }
        }
    }
    __syncthreads();
    for (int i = threadIdx.x; i < 1024; i += 256) {
        unsigned c = s_hist[i];
        if (c) atomicAdd(&g_hist[i], c);
    }
    __threadfence();
    if (threadIdx.x == 0) s_last = (atomicAdd(&g_done3, 1) == gridDim.x - 1) ? 1u : 0u;
    __syncthreads();
    if (s_last) {
        __threadfence();
        select_pass(0, 10);
        if (threadIdx.x == 0) g_done3 = 0;
    }
}

// ---------------- threshold + 7x7 NMS: 64x32 tiles, prefix/suffix window max ----------------
__global__ __launch_bounds__(256) void k_pool(float* __restrict__ out) {
    __shared__ float sxt[70][40];   // 70 x 38 used
    __shared__ float srm[70][33];
    const int bx = blockIdx.x, by = blockIdx.y, n = blockIdx.z;
    const int r0 = by * 64, c0 = bx * 32;
    const float* __restrict__ Ri = g_R + (size_t)n * HH * WW;
    const float med = g_med;
    const float NEG_INF = __int_as_float(0xFF800000);
    const int t = threadIdx.x;

    const bool interior = (bx > 0) && (bx < WW/32 - 1) && (by > 0) && (by < HH/64 - 1);

    if (interior) {
        const float* base = Ri + (size_t)(r0 - 3) * WW + (c0 - 3);
        for (int idx = t; idx < 70*38; idx += 256) {
            int i = idx / 38, j = idx % 38;
            float R = base[(size_t)i * WW + j];
            sxt[i][j] = (R > med) ? R : 0.f;
        }
    } else {
        for (int idx = t; idx < 70*38; idx += 256) {
            int i = idx / 38, j = idx % 38;
            int gr = r0 + i - 3, gc = c0 + j - 3;
            float v = NEG_INF;
            if (gr >= 0 && gr < HH && gc >= 0 && gc < WW) {
                float R = Ri[(size_t)gr * WW + gc];
                v = (R > med) ? R : 0.f;
            }
            sxt[i][j] = v;
        }
    }
    __syncthreads();

    // horizontal 7-max: rows 0..69, out cols 0..31
    for (int idx = t; idx < 70*32; idx += 256) {
        int i = idx >> 5, j = idx & 31;
        float m = sxt[i][j];
        #pragma unroll
        for (int k = 1; k < 7; k++) m = fmaxf(m, sxt[i][j+k]);
        srm[i][j] = m;
    }
    __syncthreads();

    // vertical 7-max over 14-row window via prefix/suffix, 8 outputs/thread
    {
        const int col = t & 31;
        const int r0l = (t >> 5) * 8;
        float v[14];
        #pragma unroll
        for (int k = 0; k < 14; k++) v[k] = srm[r0l + k][col];
        float suf[7], pre[7];
        suf[6] = v[6];
        #pragma unroll
        for (int i = 5; i >= 0; i--) suf[i] = fmaxf(v[i], suf[i+1]);
        pre[0] = v[7];
        #pragma unroll
        for (int i = 1; i < 7; i++) pre[i] = fmaxf(pre[i-1], v[7+i]);

        size_t obase = (size_t)n * HH * WW + (size_t)(r0 + r0l) * WW + (c0 + col);
        #pragma unroll
        for (int o = 0; o < 8; o++) {
            float m = (o == 0) ? suf[0] : ((o == 7) ? pre[6] : fmaxf(suf[o], pre[o-1]));
            float xt = sxt[r0l + o + 3][col + 3];
            out[obase + (size_t)o * WW] = (xt == m) ? xt : 0.f;
        }
    }
}

// ---------------- launch ----------------
extern "C" void kernel_launch(void* const* d_in, const int* in_sizes, int n_in,
                              void* d_out, int out_size) {
    const float* x     = (const float*)d_in[0];
    const float* gauss = (const float*)d_in[2];
    float* out = (float*)d_out;

    static int configured = 0;
    if (!configured) {
        cudaFuncSetAttribute(k_harris, cudaFuncAttributeMaxDynamicSharedMemorySize, SMEM_BYTES);
        cudaFuncSetAttribute(k_harris, cudaFuncAttributePreferredSharedMemoryCarveout, 100);
        configured = 1;
    }

    dim3 gh(WW/TC, HH/TR, NIMG);
    k_harris<<<gh, 256, SMEM_BYTES>>>(x, gauss);

    k_hist2<<<2048, 256>>>();
    k_hist3<<<2048, 256>>>();

    dim3 gp(WW/32, HH/64, NIMG);
    k_pool<<<gp, 256>>>(out);
}